// round 16
// baseline (speedup 1.0000x reference)
#include <cuda_runtime.h>
#include <cstdint>

#define BB 64
#define PP 25000
#define TT 16
#define CC 81

#define LROWS 64
#define LTILES 8
#define NTILE ((PP + LROWS - 1) / LROWS)          // 391
#define LNBX ((NTILE + LTILES - 1) / LTILES)      // 49
#define MCAP 8192                                  // mine fast-path candidate capacity

// ---------------- scratch ----------------
__device__ float               g_bt_ov[BB * PP];
__device__ unsigned char       g_bt_idx[BB * PP];
__device__ unsigned long long  g_bp_key[BB * TT];
__device__ float               g_loss_c[BB * PP];
__device__ int                 g_hist1[BB * 2048];
__device__ double              g_histsum[BB * 2048];
__device__ int                 g_num_pos[BB];
__device__ int                 g_total_pos;
__device__ int                 g_ticket;
__device__ double              g_loss_l;
__device__ double              g_ce_pos;
__device__ double              g_ce_neg;

// ---------------- async helpers ----------------
__device__ __forceinline__ unsigned smem_u32(const void* p) {
    return (unsigned)__cvta_generic_to_shared(p);
}
__device__ __forceinline__ void mbar_init(unsigned mbar, unsigned count) {
    asm volatile("mbarrier.init.shared.b64 [%0], %1;" :: "r"(mbar), "r"(count) : "memory");
}
__device__ __forceinline__ void mbar_expect_tx(unsigned mbar, unsigned bytes) {
    asm volatile("mbarrier.arrive.expect_tx.shared.b64 _, [%0], %1;"
                 :: "r"(mbar), "r"(bytes) : "memory");
}
__device__ __forceinline__ void bulk_g2s(unsigned dst, const void* src,
                                         unsigned bytes, unsigned mbar) {
    asm volatile("cp.async.bulk.shared::cluster.global.mbarrier::complete_tx::bytes "
                 "[%0], [%1], %2, [%3];"
                 :: "r"(dst), "l"(src), "r"(bytes), "r"(mbar) : "memory");
}
__device__ __forceinline__ void mbar_wait(unsigned mbar, unsigned parity) {
    asm volatile(
        "{\n\t.reg .pred P;\n\t"
        "WL%=:\n\t"
        "mbarrier.try_wait.parity.acquire.cta.shared::cta.b64 P, [%0], %1, 0x989680;\n\t"
        "@P bra.uni WD%=;\n\t"
        "bra.uni WL%=;\n\t"
        "WD%=:\n\t}"
        :: "r"(mbar), "r"(parity) : "memory");
}

// ---------------- match (R9): REDUX per-prior + per-truth ----------------
__global__ void match_kernel(const float* __restrict__ priors,
                             const float* __restrict__ targets) {
    const int b = blockIdx.y;
    const int p = blockIdx.x * 256 + threadIdx.x;
    const int lane = threadIdx.x & 31;
    __shared__ float s_t[TT][4];
    __shared__ float s_ta[TT];
    __shared__ unsigned long long s_key[TT];

    if (threadIdx.x < TT) {
        const float* tr = targets + ((size_t)b * TT + threadIdx.x) * 5;
        float x0 = tr[0], y0 = tr[1], x1 = tr[2], y1 = tr[3];
        s_t[threadIdx.x][0] = x0; s_t[threadIdx.x][1] = y0;
        s_t[threadIdx.x][2] = x1; s_t[threadIdx.x][3] = y1;
        s_ta[threadIdx.x] = (x1 - x0) * (y1 - y0);
        s_key[threadIdx.x] = 0ULL;
    }
    __syncthreads();

    const bool valid = (p < PP);
    float px0 = 0.f, py0 = 0.f, px1 = 0.f, py1 = 0.f, pa = 0.f;
    if (valid) {
        float4 pr = ((const float4*)priors)[p];
        px0 = pr.x - pr.z * 0.5f; py0 = pr.y - pr.w * 0.5f;
        px1 = pr.x + pr.z * 0.5f; py1 = pr.y + pr.w * 0.5f;
        pa  = (px1 - px0) * (py1 - py0);
    }

    float best = -1.0f;
    int   bi   = 0;

    #pragma unroll
    for (int t = 0; t < TT; t++) {
        unsigned ib = 0;
        if (valid) {
            float lx = fmaxf(s_t[t][0], px0), ly = fmaxf(s_t[t][1], py0);
            float rx = fminf(s_t[t][2], px1), ry = fminf(s_t[t][3], py1);
            float iw = fmaxf(rx - lx, 0.0f), ih = fmaxf(ry - ly, 0.0f);
            float inter = iw * ih;
            float iou = inter / (s_ta[t] + pa - inter);
            if (iou > best) { best = iou; bi = t; }           // strict > -> first max
            ib = __float_as_uint(iou);                        // iou >= 0 -> order-preserving
        }
        unsigned wmax = __reduce_max_sync(0xffffffffu, ib);
        unsigned cp   = (valid && ib == wmax) ? (unsigned)p : 0xFFFFFFFFu;
        unsigned pmin = __reduce_min_sync(0xffffffffu, cp);   // tie -> smallest p
        if (lane == 0) {
            unsigned long long key = (((unsigned long long)wmax) << 32) | (unsigned)(~pmin);
            atomicMax(&s_key[t], key);
        }
    }

    if (valid) {
        g_bt_ov[(size_t)b * PP + p]  = best;
        g_bt_idx[(size_t)b * PP + p] = (unsigned char)bi;
    }
    __syncthreads();
    if (threadIdx.x < TT) atomicMax(&g_bp_key[b * TT + threadIdx.x], s_key[threadIdx.x]);
}

// ---------------- force each truth's best prior (last j wins) ----------------
__global__ void force_kernel() {
    int b = threadIdx.x;
    if (b >= BB) return;
    for (int j = 0; j < TT; j++) {
        unsigned long long key = g_bp_key[b * TT + j];
        unsigned p = ~(unsigned)(key & 0xFFFFFFFFULL);
        g_bt_ov[(size_t)b * PP + p]  = 2.0f;
        g_bt_idx[(size_t)b * PP + p] = (unsigned char)j;
    }
}

// ---------------- fused loss (R9) + per-bin count & value-sum histograms ----------------
__global__ void __launch_bounds__(256, 5) loss_kernel(
        const float* __restrict__ loc_data,
        const float* __restrict__ conf_data,
        const float* __restrict__ priors,
        const float* __restrict__ targets) {
    const int b   = blockIdx.y;
    const int tid = threadIdx.x;
    const int t0  = blockIdx.x * LTILES;
    const int S   = min(LTILES, NTILE - t0);

    __shared__ float s_buf[2][LROWS * CC];                 // 2 x 20736 B
    __shared__ float s_tr[TT][5];
    __shared__ float s_ll[8], s_cep[8];
    __shared__ int   s_pos[8];
    __shared__ __align__(8) unsigned long long s_mbar[2];

    if (tid < TT * 5)
        ((float*)s_tr)[tid] = targets[(size_t)b * TT * 5 + tid];

    const unsigned mb[2]  = { smem_u32(&s_mbar[0]), smem_u32(&s_mbar[1]) };
    const unsigned sb[2]  = { smem_u32(&s_buf[0][0]), smem_u32(&s_buf[1][0]) };
    if (tid == 0) { mbar_init(mb[0], 1); mbar_init(mb[1], 1); }
    __syncthreads();

    const float* cbase = conf_data + (size_t)b * PP * CC;

    if (tid == 0) {
        const int row0 = t0 * LROWS;
        const unsigned bytes = (unsigned)(min(LROWS, PP - row0) * CC * 4);
        mbar_expect_tx(mb[0], bytes);
        bulk_g2s(sb[0], cbase + (size_t)row0 * CC, bytes, mb[0]);
    }

    float my_ll = 0.f, my_cep = 0.f;
    int   my_pos = 0;

    const int strip_l = tid >> 4;
    const int h       = tid & 15;
    const int fs      = 20 * h;
    const int nf      = (h == 15) ? 6 : 5;
    const int fe      = fs + 4 * nf;
    const int splitf  = min((fs / 81 + 1) * 81, fe);
    const int r       = h >> 2;
    const bool rowlead = ((h & 3) == 0);

    for (int s = 0; s < S; s++) {
        if (s + 1 < S && tid == 0) {
            const int row0n = (t0 + s + 1) * LROWS;
            const unsigned bytes = (unsigned)(min(LROWS, PP - row0n) * CC * 4);
            mbar_expect_tx(mb[(s + 1) & 1], bytes);
            bulk_g2s(sb[(s + 1) & 1], cbase + (size_t)row0n * CC, bytes, mb[(s + 1) & 1]);
        }

        const int row0 = (t0 + s) * LROWS;
        const int rows = min(LROWS, PP - row0);
        const bool sact = (strip_l * 4 < rows);
        const int  prow = row0 + strip_l * 4 + r;

        float ovv = 0.f; int tiv = 0;
        if (rowlead && sact) {
            const size_t off = (size_t)b * PP + prow;
            ovv = g_bt_ov[off];
            tiv = g_bt_idx[off];
        }

        mbar_wait(mb[s & 1], (unsigned)((s >> 1) & 1));

        const float* base = s_buf[s & 1];
        float accA = 0.f, accB = 0.f;
        if (sact) {
            const float* tp = base + strip_l * 324 + fs;
            #pragma unroll
            for (int i = 0; i < 6; i++) {
                if (i < nf) {
                    float4 v = *(const float4*)(tp + 4 * i);
                    float e0 = __expf(v.x), e1 = __expf(v.y);
                    float e2 = __expf(v.z), e3 = __expf(v.w);
                    float sv = (e0 + e1) + (e2 + e3);
                    int w = fs + 4 * i;
                    if (w + 4 <= splitf)      accA += sv;
                    else if (w >= splitf)     accB += sv;
                    else {
                        accA += (w     < splitf ? e0 : 0.f) + (w + 1 < splitf ? e1 : 0.f)
                              + (w + 2 < splitf ? e2 : 0.f) + (w + 3 < splitf ? e3 : 0.f);
                        accB += (w     >= splitf ? e0 : 0.f) + (w + 1 >= splitf ? e1 : 0.f)
                              + (w + 2 >= splitf ? e2 : 0.f) + (w + 3 >= splitf ? e3 : 0.f);
                    }
                }
            }
        }

        float a1 = __shfl_down_sync(0xffffffffu, accA, 1);
        float a2 = __shfl_down_sync(0xffffffffu, accA, 2);
        float a3 = __shfl_down_sync(0xffffffffu, accA, 3);
        float a4 = __shfl_down_sync(0xffffffffu, accA, 4);
        float basev = (h == 0) ? accA : accB;
        float tot = basev + a1 + a2 + a3 + ((rowlead && r < 3) ? a4 : 0.f);

        if (rowlead && sact) {
            float lse = __logf(tot);
            bool pos = (ovv >= 0.5f);
            int  ct  = pos ? ((int)s_tr[tiv][4] + 1) : 0;
            float ce = lse - base[(strip_l * 4 + r) * 81 + ct];
            float lc = pos ? 0.f : ce;
            g_loss_c[(size_t)b * PP + prow] = lc;
            const int bin = (int)(__float_as_uint(lc) >> 21);
            atomicAdd(&g_hist1[b * 2048 + bin], 1);
            atomicAdd(&g_histsum[b * 2048 + bin], (double)lc);
            if (pos) {
                my_pos++;
                my_cep += ce;
                float4 pr = ((const float4*)priors)[prow];
                float tx0 = s_tr[tiv][0], ty0 = s_tr[tiv][1];
                float tx1 = s_tr[tiv][2], ty1 = s_tr[tiv][3];
                float gx = ((tx0 + tx1) * 0.5f - pr.x) / (0.1f * pr.z);
                float gy = ((ty0 + ty1) * 0.5f - pr.y) / (0.1f * pr.w);
                float gw = __logf((tx1 - tx0) / pr.z) * 5.0f;
                float gh = __logf((ty1 - ty0) / pr.w) * 5.0f;
                float4 ld = ((const float4*)loc_data)[(size_t)b * PP + prow];
                float d, ad;
                d = ld.x - gx; ad = fabsf(d); my_ll += (ad < 1.f) ? 0.5f * d * d : ad - 0.5f;
                d = ld.y - gy; ad = fabsf(d); my_ll += (ad < 1.f) ? 0.5f * d * d : ad - 0.5f;
                d = ld.z - gw; ad = fabsf(d); my_ll += (ad < 1.f) ? 0.5f * d * d : ad - 0.5f;
                d = ld.w - gh; ad = fabsf(d); my_ll += (ad < 1.f) ? 0.5f * d * d : ad - 0.5f;
            }
        }
        __syncthreads();
    }

    #pragma unroll
    for (int o = 16; o > 0; o >>= 1) {
        my_ll  += __shfl_xor_sync(0xffffffffu, my_ll, o);
        my_cep += __shfl_xor_sync(0xffffffffu, my_cep, o);
        my_pos += __shfl_xor_sync(0xffffffffu, my_pos, o);
    }
    const int lane = tid & 31, warp = tid >> 5;
    if (lane == 0) { s_ll[warp] = my_ll; s_cep[warp] = my_cep; s_pos[warp] = my_pos; }
    __syncthreads();
    if (tid == 0) {
        float ll = 0.f, cep = 0.f; int np = 0;
        #pragma unroll
        for (int w = 0; w < 8; w++) { ll += s_ll[w]; cep += s_cep[w]; np += s_pos[w]; }
        if (np) {
            atomicAdd(&g_loss_l, (double)ll);
            atomicAdd(&g_ce_pos, (double)cep);
            atomicAdd(&g_num_pos[b], np);
            atomicAdd(&g_total_pos, np);
        }
    }
}

// ---------------- mining: 1-sweep compact fast path (+fallback) + finalize ----------------
__global__ void mine_kernel(float* __restrict__ out) {
    const int b   = blockIdx.x;
    const int tid = threadIdx.x;
    __shared__ int      hist[2048];
    __shared__ int      s_group[64];
    __shared__ unsigned s_prefix;
    __shared__ int      s_kk;
    __shared__ int      s_cnt;
    __shared__ int      s_cc;                   // dedicated compaction counter (R15 race fix)
    __shared__ int      s_last;
    __shared__ unsigned s_cand[MCAP];           // 32 KB
    __shared__ double   sdl[32];

    int np = g_num_pos[b];
    int k  = min(3 * np, PP - 1);
    const int lane = tid & 31, w = tid >> 5;

    if (k > 0) {
        const float* lc = g_loss_c + (size_t)b * PP;

        // pass 1: precomputed count histogram (bits 31..21); reset counts
        hist[tid] = g_hist1[b * 2048 + tid];
        hist[tid + 1024] = g_hist1[b * 2048 + 1024 + tid];
        g_hist1[b * 2048 + tid] = 0;
        g_hist1[b * 2048 + 1024 + tid] = 0;
        __syncthreads();
        if (tid < 64) {
            int s = 0;
            #pragma unroll
            for (int j = 0; j < 32; j++) s += hist[tid * 32 + j];
            s_group[tid] = s;
        }
        __syncthreads();
        if (tid == 0) {
            int cum = 0, g = 63;
            for (; g > 0; g--) {
                if (cum + s_group[g] >= k) break;
                cum += s_group[g];
            }
            int x = g * 32 + 31;
            for (;; x--) {
                int hv = hist[x];
                if (cum + hv >= k || x == g * 32) break;
                cum += hv;
            }
            s_prefix = (unsigned)x;              // bin index for now
            s_kk  = k - cum;
            s_cnt = hist[x];
            s_cc  = 0;                           // compaction counter, init here (pre-barrier)
        }
        __syncthreads();
        const unsigned bin = s_prefix;
        int kk = s_kk;
        const int count = s_cnt;                 // stable: s_cnt never rewritten below

        // read + reset value-sum histogram; keep above-bin partial per thread
        double hs = 0.0;
        {
            int i0 = tid, i1 = tid + 1024;
            double v0 = g_histsum[b * 2048 + i0];
            double v1 = g_histsum[b * 2048 + i1];
            g_histsum[b * 2048 + i0] = 0.0;
            g_histsum[b * 2048 + i1] = 0.0;
            if (i0 > (int)bin) hs += v0;
            if (i1 > (int)bin) hs += v1;
        }

        if (count <= MCAP) {
            // ---- fast path: ONE global sweep compacts in-bin candidates ----
            {
                int i = tid;
                for (; i + 7 * 1024 < PP; i += 8 * 1024) {
                    unsigned kx[8];
                    #pragma unroll
                    for (int u = 0; u < 8; u++) kx[u] = __float_as_uint(lc[i + u * 1024]);
                    #pragma unroll
                    for (int u = 0; u < 8; u++)
                        if ((kx[u] >> 21) == bin) s_cand[atomicAdd(&s_cc, 1)] = kx[u];
                }
                for (; i < PP; i += 1024) {
                    unsigned key = __float_as_uint(lc[i]);
                    if ((key >> 21) == bin) s_cand[atomicAdd(&s_cc, 1)] = key;
                }
            }
            __syncthreads();

            // refine bits 20..10 over candidates (2048 bins)
            hist[tid] = 0; hist[tid + 1024] = 0;
            __syncthreads();
            for (int i = tid; i < count; i += 1024)
                atomicAdd(&hist[(s_cand[i] >> 10) & 2047], 1);
            __syncthreads();
            if (tid < 64) {
                int s = 0;
                #pragma unroll
                for (int j = 0; j < 32; j++) s += hist[tid * 32 + j];
                s_group[tid] = s;
            }
            __syncthreads();
            if (tid == 0) {
                int cum = 0, g = 63;
                for (; g > 0; g--) {
                    if (cum + s_group[g] >= kk) break;
                    cum += s_group[g];
                }
                int x = g * 32 + 31;
                for (;; x--) {
                    int hv = hist[x];
                    if (cum + hv >= kk || x == g * 32) break;
                    cum += hv;
                }
                s_prefix = (bin << 21) | ((unsigned)x << 10);
                s_kk = kk - cum;
            }
            __syncthreads();
            unsigned prefix = s_prefix;
            kk = s_kk;

            // refine bits 9..0 over candidates (1024 bins)
            hist[tid] = 0;
            __syncthreads();
            const unsigned hm = 0xFFFFFFFFu << 10;
            for (int i = tid; i < count; i += 1024) {
                unsigned key = s_cand[i];
                if ((key & hm) == prefix) atomicAdd(&hist[key & 1023], 1);
            }
            __syncthreads();
            if (tid < 32) {
                int s = 0;
                #pragma unroll
                for (int j = 0; j < 32; j++) s += hist[tid * 32 + j];
                s_group[tid] = s;
            }
            __syncthreads();
            if (tid == 0) {
                int cum = 0, g = 31;
                for (; g > 0; g--) {
                    if (cum + s_group[g] >= kk) break;
                    cum += s_group[g];
                }
                int x = g * 32 + 31;
                for (;; x--) {
                    int hv = hist[x];
                    if (cum + hv >= kk || x == g * 32) break;
                    cum += hv;
                }
                s_prefix = prefix | (unsigned)x;
                s_kk = kk - cum;
            }
            __syncthreads();
            prefix = s_prefix;
            kk = s_kk;

            // sum candidates above threshold + hs partials
            double local = hs;
            for (int i = tid; i < count; i += 1024) {
                unsigned key = s_cand[i];
                if (key > prefix) local += (double)__uint_as_float(key);
            }
            #pragma unroll
            for (int o = 16; o > 0; o >>= 1) local += __shfl_xor_sync(0xffffffffu, local, o);
            if (lane == 0) sdl[w] = local;
            __syncthreads();
            if (tid == 0) {
                double tot = 0.0;
                for (int i = 0; i < 32; i++) tot += sdl[i];
                tot += (double)kk * (double)__uint_as_float(prefix);
                atomicAdd(&g_ce_neg, tot);
            }
        } else {
            // ---- fallback: radix passes + global sum sweep (hs unused) ----
            unsigned prefix = bin << 21;
            const int shifts[2] = {10, 0};
            const int nbits [2] = {11, 10};
            #pragma unroll
            for (int pass = 0; pass < 2; pass++) {
                const int shift = shifts[pass];
                const int nb    = 1 << nbits[pass];
                hist[tid] = 0; hist[tid + 1024] = 0;
                __syncthreads();
                const unsigned hmask = 0xFFFFFFFFu << (shift + nbits[pass]);
                const unsigned bmask = (unsigned)(nb - 1);

                int i = tid;
                for (; i + 7 * 1024 < PP; i += 8 * 1024) {
                    unsigned kx[8];
                    #pragma unroll
                    for (int u = 0; u < 8; u++) kx[u] = __float_as_uint(lc[i + u * 1024]);
                    #pragma unroll
                    for (int u = 0; u < 8; u++)
                        if ((kx[u] & hmask) == prefix)
                            atomicAdd(&hist[(kx[u] >> shift) & bmask], 1);
                }
                for (; i < PP; i += 1024) {
                    unsigned key = __float_as_uint(lc[i]);
                    if ((key & hmask) == prefix) atomicAdd(&hist[(key >> shift) & bmask], 1);
                }
                __syncthreads();

                const int ngroups = nb >> 5;
                if (tid < ngroups) {
                    int s = 0;
                    #pragma unroll
                    for (int j = 0; j < 32; j++) s += hist[tid * 32 + j];
                    s_group[tid] = s;
                }
                __syncthreads();
                if (tid == 0) {
                    int cum = 0, g = ngroups - 1;
                    for (; g > 0; g--) {
                        if (cum + s_group[g] >= kk) break;
                        cum += s_group[g];
                    }
                    int x = g * 32 + 31;
                    for (;; x--) {
                        int hv = hist[x];
                        if (cum + hv >= kk || x == g * 32) break;
                        cum += hv;
                    }
                    s_prefix = prefix | ((unsigned)x << shift);
                    s_kk = kk - cum;
                }
                __syncthreads();
                prefix = s_prefix;
                kk     = s_kk;
            }

            double local = 0.0;
            {
                int i = tid;
                for (; i + 7 * 1024 < PP; i += 8 * 1024) {
                    float a[8];
                    #pragma unroll
                    for (int u = 0; u < 8; u++) a[u] = lc[i + u * 1024];
                    #pragma unroll
                    for (int u = 0; u < 8; u++)
                        if (__float_as_uint(a[u]) > prefix) local += (double)a[u];
                }
                for (; i < PP; i += 1024) {
                    float v = lc[i];
                    if (__float_as_uint(v) > prefix) local += (double)v;
                }
            }
            #pragma unroll
            for (int o = 16; o > 0; o >>= 1) local += __shfl_xor_sync(0xffffffffu, local, o);
            if (lane == 0) sdl[w] = local;
            __syncthreads();
            if (tid == 0) {
                double tot = 0.0;
                for (int i = 0; i < 32; i++) tot += sdl[i];
                tot += (double)kk * (double)__uint_as_float(prefix);
                atomicAdd(&g_ce_neg, tot);
            }
        }
    } else {
        // reset this batch's histograms for the next replay
        g_hist1[b * 2048 + tid] = 0;
        g_hist1[b * 2048 + 1024 + tid] = 0;
        g_histsum[b * 2048 + tid] = 0.0;
        g_histsum[b * 2048 + 1024 + tid] = 0.0;
    }

    // ---- last-block finalize + state reset ----
    __syncthreads();
    if (tid == 0) {
        __threadfence();
        s_last = (atomicAdd(&g_ticket, 1) == BB - 1) ? 1 : 0;
    }
    __syncthreads();
    if (s_last) {
        if (tid == 0) {
            double N = (double)g_total_pos;
            if (N < 1.0) N = 1.0;
            out[0] = (float)(g_loss_l / N);
            out[1] = (float)((g_ce_pos + g_ce_neg) / N);
            g_total_pos = 0; g_loss_l = 0.0; g_ce_pos = 0.0; g_ce_neg = 0.0;
            g_ticket = 0;
        }
        g_bp_key[tid] = 0ULL;                   // BB*TT == 1024
        if (tid < BB) g_num_pos[tid] = 0;
    }
}

extern "C" void kernel_launch(void* const* d_in, const int* in_sizes, int n_in,
                              void* d_out, int out_size) {
    const float* loc_data  = (const float*)d_in[0];   // [B,P,4]
    const float* conf_data = (const float*)d_in[1];   // [B,P,81]
    const float* priors    = (const float*)d_in[2];   // [P,4]
    const float* targets   = (const float*)d_in[3];   // [B,T,5]
    float* out = (float*)d_out;

    match_kernel<<<dim3((PP + 255) / 256, BB), 256>>>(priors, targets);
    force_kernel<<<1, BB>>>();
    loss_kernel<<<dim3(LNBX, BB), 256>>>(loc_data, conf_data, priors, targets);
    mine_kernel<<<BB, 1024>>>(out);
}

// round 17
// speedup vs baseline: 1.1280x; 1.1280x over previous
#include <cuda_runtime.h>
#include <cstdint>

#define BB 64
#define PP 25000
#define TT 16
#define CC 81

#define LROWS 64
#define LTILES 8
#define NTILE ((PP + LROWS - 1) / LROWS)          // 391
#define LNBX ((NTILE + LTILES - 1) / LTILES)      // 49
#define MCAP 8192                                  // mine fast-path candidate capacity

// ---------------- scratch ----------------
__device__ float               g_bt_ov[BB * PP];
__device__ unsigned char       g_bt_idx[BB * PP];
__device__ unsigned long long  g_bp_key[BB * TT];
__device__ float               g_loss_c[BB * PP];
__device__ int                 g_hist1[BB * 2048];
__device__ int                 g_num_pos[BB];
__device__ int                 g_total_pos;
__device__ int                 g_ticket;
__device__ double              g_loss_l;
__device__ double              g_ce_pos;
__device__ double              g_ce_neg;

// ---------------- async helpers ----------------
__device__ __forceinline__ unsigned smem_u32(const void* p) {
    return (unsigned)__cvta_generic_to_shared(p);
}
__device__ __forceinline__ void mbar_init(unsigned mbar, unsigned count) {
    asm volatile("mbarrier.init.shared.b64 [%0], %1;" :: "r"(mbar), "r"(count) : "memory");
}
__device__ __forceinline__ void mbar_expect_tx(unsigned mbar, unsigned bytes) {
    asm volatile("mbarrier.arrive.expect_tx.shared.b64 _, [%0], %1;"
                 :: "r"(mbar), "r"(bytes) : "memory");
}
__device__ __forceinline__ void bulk_g2s(unsigned dst, const void* src,
                                         unsigned bytes, unsigned mbar) {
    asm volatile("cp.async.bulk.shared::cluster.global.mbarrier::complete_tx::bytes "
                 "[%0], [%1], %2, [%3];"
                 :: "r"(dst), "l"(src), "r"(bytes), "r"(mbar) : "memory");
}
__device__ __forceinline__ void mbar_wait(unsigned mbar, unsigned parity) {
    asm volatile(
        "{\n\t.reg .pred P;\n\t"
        "WL%=:\n\t"
        "mbarrier.try_wait.parity.acquire.cta.shared::cta.b64 P, [%0], %1, 0x989680;\n\t"
        "@P bra.uni WD%=;\n\t"
        "bra.uni WL%=;\n\t"
        "WD%=:\n\t}"
        :: "r"(mbar), "r"(parity) : "memory");
}

// ---------------- match (R9): REDUX per-prior + per-truth ----------------
__global__ void match_kernel(const float* __restrict__ priors,
                             const float* __restrict__ targets) {
    const int b = blockIdx.y;
    const int p = blockIdx.x * 256 + threadIdx.x;
    const int lane = threadIdx.x & 31;
    __shared__ float s_t[TT][4];
    __shared__ float s_ta[TT];
    __shared__ unsigned long long s_key[TT];

    if (threadIdx.x < TT) {
        const float* tr = targets + ((size_t)b * TT + threadIdx.x) * 5;
        float x0 = tr[0], y0 = tr[1], x1 = tr[2], y1 = tr[3];
        s_t[threadIdx.x][0] = x0; s_t[threadIdx.x][1] = y0;
        s_t[threadIdx.x][2] = x1; s_t[threadIdx.x][3] = y1;
        s_ta[threadIdx.x] = (x1 - x0) * (y1 - y0);
        s_key[threadIdx.x] = 0ULL;
    }
    __syncthreads();

    const bool valid = (p < PP);
    float px0 = 0.f, py0 = 0.f, px1 = 0.f, py1 = 0.f, pa = 0.f;
    if (valid) {
        float4 pr = ((const float4*)priors)[p];
        px0 = pr.x - pr.z * 0.5f; py0 = pr.y - pr.w * 0.5f;
        px1 = pr.x + pr.z * 0.5f; py1 = pr.y + pr.w * 0.5f;
        pa  = (px1 - px0) * (py1 - py0);
    }

    float best = -1.0f;
    int   bi   = 0;

    #pragma unroll
    for (int t = 0; t < TT; t++) {
        unsigned ib = 0;
        if (valid) {
            float lx = fmaxf(s_t[t][0], px0), ly = fmaxf(s_t[t][1], py0);
            float rx = fminf(s_t[t][2], px1), ry = fminf(s_t[t][3], py1);
            float iw = fmaxf(rx - lx, 0.0f), ih = fmaxf(ry - ly, 0.0f);
            float inter = iw * ih;
            float iou = inter / (s_ta[t] + pa - inter);
            if (iou > best) { best = iou; bi = t; }           // strict > -> first max
            ib = __float_as_uint(iou);                        // iou >= 0 -> order-preserving
        }
        unsigned wmax = __reduce_max_sync(0xffffffffu, ib);
        unsigned cp   = (valid && ib == wmax) ? (unsigned)p : 0xFFFFFFFFu;
        unsigned pmin = __reduce_min_sync(0xffffffffu, cp);   // tie -> smallest p
        if (lane == 0) {
            unsigned long long key = (((unsigned long long)wmax) << 32) | (unsigned)(~pmin);
            atomicMax(&s_key[t], key);
        }
    }

    if (valid) {
        g_bt_ov[(size_t)b * PP + p]  = best;
        g_bt_idx[(size_t)b * PP + p] = (unsigned char)bi;
    }
    __syncthreads();
    if (threadIdx.x < TT) atomicMax(&g_bp_key[b * TT + threadIdx.x], s_key[threadIdx.x]);
}

// ---------------- force each truth's best prior (last j wins) ----------------
__global__ void force_kernel() {
    int b = threadIdx.x;
    if (b >= BB) return;
    for (int j = 0; j < TT; j++) {
        unsigned long long key = g_bp_key[b * TT + j];
        unsigned p = ~(unsigned)(key & 0xFFFFFFFFULL);
        g_bt_ov[(size_t)b * PP + p]  = 2.0f;
        g_bt_idx[(size_t)b * PP + p] = (unsigned char)j;
    }
}

// ---------------- fused loss (R14, measured 101.5us): count histogram only ----------------
__global__ void __launch_bounds__(256, 5) loss_kernel(
        const float* __restrict__ loc_data,
        const float* __restrict__ conf_data,
        const float* __restrict__ priors,
        const float* __restrict__ targets) {
    const int b   = blockIdx.y;
    const int tid = threadIdx.x;
    const int t0  = blockIdx.x * LTILES;
    const int S   = min(LTILES, NTILE - t0);

    __shared__ float s_buf[2][LROWS * CC];                 // 2 x 20736 B
    __shared__ float s_tr[TT][5];
    __shared__ float s_ll[8], s_cep[8];
    __shared__ int   s_pos[8];
    __shared__ __align__(8) unsigned long long s_mbar[2];

    if (tid < TT * 5)
        ((float*)s_tr)[tid] = targets[(size_t)b * TT * 5 + tid];

    const unsigned mb[2]  = { smem_u32(&s_mbar[0]), smem_u32(&s_mbar[1]) };
    const unsigned sb[2]  = { smem_u32(&s_buf[0][0]), smem_u32(&s_buf[1][0]) };
    if (tid == 0) { mbar_init(mb[0], 1); mbar_init(mb[1], 1); }
    __syncthreads();

    const float* cbase = conf_data + (size_t)b * PP * CC;

    if (tid == 0) {
        const int row0 = t0 * LROWS;
        const unsigned bytes = (unsigned)(min(LROWS, PP - row0) * CC * 4);
        mbar_expect_tx(mb[0], bytes);
        bulk_g2s(sb[0], cbase + (size_t)row0 * CC, bytes, mb[0]);
    }

    float my_ll = 0.f, my_cep = 0.f;
    int   my_pos = 0;

    const int strip_l = tid >> 4;
    const int h       = tid & 15;
    const int fs      = 20 * h;
    const int nf      = (h == 15) ? 6 : 5;
    const int fe      = fs + 4 * nf;
    const int splitf  = min((fs / 81 + 1) * 81, fe);
    const int r       = h >> 2;
    const bool rowlead = ((h & 3) == 0);

    for (int s = 0; s < S; s++) {
        if (s + 1 < S && tid == 0) {
            const int row0n = (t0 + s + 1) * LROWS;
            const unsigned bytes = (unsigned)(min(LROWS, PP - row0n) * CC * 4);
            mbar_expect_tx(mb[(s + 1) & 1], bytes);
            bulk_g2s(sb[(s + 1) & 1], cbase + (size_t)row0n * CC, bytes, mb[(s + 1) & 1]);
        }

        const int row0 = (t0 + s) * LROWS;
        const int rows = min(LROWS, PP - row0);
        const bool sact = (strip_l * 4 < rows);
        const int  prow = row0 + strip_l * 4 + r;

        float ovv = 0.f; int tiv = 0;
        if (rowlead && sact) {
            const size_t off = (size_t)b * PP + prow;
            ovv = g_bt_ov[off];
            tiv = g_bt_idx[off];
        }

        mbar_wait(mb[s & 1], (unsigned)((s >> 1) & 1));

        const float* base = s_buf[s & 1];
        float accA = 0.f, accB = 0.f;
        if (sact) {
            const float* tp = base + strip_l * 324 + fs;
            #pragma unroll
            for (int i = 0; i < 6; i++) {
                if (i < nf) {
                    float4 v = *(const float4*)(tp + 4 * i);
                    float e0 = __expf(v.x), e1 = __expf(v.y);
                    float e2 = __expf(v.z), e3 = __expf(v.w);
                    float sv = (e0 + e1) + (e2 + e3);
                    int w = fs + 4 * i;
                    if (w + 4 <= splitf)      accA += sv;
                    else if (w >= splitf)     accB += sv;
                    else {
                        accA += (w     < splitf ? e0 : 0.f) + (w + 1 < splitf ? e1 : 0.f)
                              + (w + 2 < splitf ? e2 : 0.f) + (w + 3 < splitf ? e3 : 0.f);
                        accB += (w     >= splitf ? e0 : 0.f) + (w + 1 >= splitf ? e1 : 0.f)
                              + (w + 2 >= splitf ? e2 : 0.f) + (w + 3 >= splitf ? e3 : 0.f);
                    }
                }
            }
        }

        float a1 = __shfl_down_sync(0xffffffffu, accA, 1);
        float a2 = __shfl_down_sync(0xffffffffu, accA, 2);
        float a3 = __shfl_down_sync(0xffffffffu, accA, 3);
        float a4 = __shfl_down_sync(0xffffffffu, accA, 4);
        float basev = (h == 0) ? accA : accB;
        float tot = basev + a1 + a2 + a3 + ((rowlead && r < 3) ? a4 : 0.f);

        if (rowlead && sact) {
            float lse = __logf(tot);
            bool pos = (ovv >= 0.5f);
            int  ct  = pos ? ((int)s_tr[tiv][4] + 1) : 0;
            float ce = lse - base[(strip_l * 4 + r) * 81 + ct];
            float lc = pos ? 0.f : ce;
            g_loss_c[(size_t)b * PP + prow] = lc;
            atomicAdd(&g_hist1[b * 2048 + (int)(__float_as_uint(lc) >> 21)], 1);
            if (pos) {
                my_pos++;
                my_cep += ce;
                float4 pr = ((const float4*)priors)[prow];
                float tx0 = s_tr[tiv][0], ty0 = s_tr[tiv][1];
                float tx1 = s_tr[tiv][2], ty1 = s_tr[tiv][3];
                float gx = ((tx0 + tx1) * 0.5f - pr.x) / (0.1f * pr.z);
                float gy = ((ty0 + ty1) * 0.5f - pr.y) / (0.1f * pr.w);
                float gw = __logf((tx1 - tx0) / pr.z) * 5.0f;
                float gh = __logf((ty1 - ty0) / pr.w) * 5.0f;
                float4 ld = ((const float4*)loc_data)[(size_t)b * PP + prow];
                float d, ad;
                d = ld.x - gx; ad = fabsf(d); my_ll += (ad < 1.f) ? 0.5f * d * d : ad - 0.5f;
                d = ld.y - gy; ad = fabsf(d); my_ll += (ad < 1.f) ? 0.5f * d * d : ad - 0.5f;
                d = ld.z - gw; ad = fabsf(d); my_ll += (ad < 1.f) ? 0.5f * d * d : ad - 0.5f;
                d = ld.w - gh; ad = fabsf(d); my_ll += (ad < 1.f) ? 0.5f * d * d : ad - 0.5f;
            }
        }
        __syncthreads();
    }

    #pragma unroll
    for (int o = 16; o > 0; o >>= 1) {
        my_ll  += __shfl_xor_sync(0xffffffffu, my_ll, o);
        my_cep += __shfl_xor_sync(0xffffffffu, my_cep, o);
        my_pos += __shfl_xor_sync(0xffffffffu, my_pos, o);
    }
    const int lane = tid & 31, warp = tid >> 5;
    if (lane == 0) { s_ll[warp] = my_ll; s_cep[warp] = my_cep; s_pos[warp] = my_pos; }
    __syncthreads();
    if (tid == 0) {
        float ll = 0.f, cep = 0.f; int np = 0;
        #pragma unroll
        for (int w = 0; w < 8; w++) { ll += s_ll[w]; cep += s_cep[w]; np += s_pos[w]; }
        if (np) {
            atomicAdd(&g_loss_l, (double)ll);
            atomicAdd(&g_ce_pos, (double)cep);
            atomicAdd(&g_num_pos[b], np);
            atomicAdd(&g_total_pos, np);
        }
    }
}

// ---------------- mining: 1-sweep (compact + above-bin sum) + finalize ----------------
__global__ void mine_kernel(float* __restrict__ out) {
    const int b   = blockIdx.x;
    const int tid = threadIdx.x;
    __shared__ int      hist[2048];
    __shared__ int      s_group[64];
    __shared__ unsigned s_prefix;
    __shared__ int      s_kk;
    __shared__ int      s_cnt;
    __shared__ int      s_cc;                   // dedicated compaction counter
    __shared__ int      s_last;
    __shared__ unsigned s_cand[MCAP];           // 32 KB
    __shared__ double   sdl[32];

    int np = g_num_pos[b];
    int k  = min(3 * np, PP - 1);
    const int lane = tid & 31, w = tid >> 5;

    if (k > 0) {
        const float* lc = g_loss_c + (size_t)b * PP;

        // pass 1: precomputed count histogram (bits 31..21); reset counts
        hist[tid] = g_hist1[b * 2048 + tid];
        hist[tid + 1024] = g_hist1[b * 2048 + 1024 + tid];
        g_hist1[b * 2048 + tid] = 0;
        g_hist1[b * 2048 + 1024 + tid] = 0;
        __syncthreads();
        if (tid < 64) {
            int s = 0;
            #pragma unroll
            for (int j = 0; j < 32; j++) s += hist[tid * 32 + j];
            s_group[tid] = s;
        }
        __syncthreads();
        if (tid == 0) {
            int cum = 0, g = 63;
            for (; g > 0; g--) {
                if (cum + s_group[g] >= k) break;
                cum += s_group[g];
            }
            int x = g * 32 + 31;
            for (;; x--) {
                int hv = hist[x];
                if (cum + hv >= k || x == g * 32) break;
                cum += hv;
            }
            s_prefix = (unsigned)x;              // bin index for now
            s_kk  = k - cum;
            s_cnt = hist[x];
            s_cc  = 0;
        }
        __syncthreads();
        const unsigned bin = s_prefix;
        int kk = s_kk;
        const int count = s_cnt;                 // stable: never rewritten below

        if (count <= MCAP) {
            // ---- ONE global sweep: compact in-bin candidates AND sum above-bin values ----
            double hs = 0.0;
            {
                int i = tid;
                for (; i + 7 * 1024 < PP; i += 8 * 1024) {
                    unsigned kx[8];
                    #pragma unroll
                    for (int u = 0; u < 8; u++) kx[u] = __float_as_uint(lc[i + u * 1024]);
                    #pragma unroll
                    for (int u = 0; u < 8; u++) {
                        unsigned hb = kx[u] >> 21;
                        if (hb > bin)       hs += (double)__uint_as_float(kx[u]);
                        else if (hb == bin) s_cand[atomicAdd(&s_cc, 1)] = kx[u];
                    }
                }
                for (; i < PP; i += 1024) {
                    unsigned key = __float_as_uint(lc[i]);
                    unsigned hb = key >> 21;
                    if (hb > bin)       hs += (double)__uint_as_float(key);
                    else if (hb == bin) s_cand[atomicAdd(&s_cc, 1)] = key;
                }
            }
            __syncthreads();

            // refine bits 20..10 over candidates (2048 bins)
            hist[tid] = 0; hist[tid + 1024] = 0;
            __syncthreads();
            for (int i = tid; i < count; i += 1024)
                atomicAdd(&hist[(s_cand[i] >> 10) & 2047], 1);
            __syncthreads();
            if (tid < 64) {
                int s = 0;
                #pragma unroll
                for (int j = 0; j < 32; j++) s += hist[tid * 32 + j];
                s_group[tid] = s;
            }
            __syncthreads();
            if (tid == 0) {
                int cum = 0, g = 63;
                for (; g > 0; g--) {
                    if (cum + s_group[g] >= kk) break;
                    cum += s_group[g];
                }
                int x = g * 32 + 31;
                for (;; x--) {
                    int hv = hist[x];
                    if (cum + hv >= kk || x == g * 32) break;
                    cum += hv;
                }
                s_prefix = (bin << 21) | ((unsigned)x << 10);
                s_kk = kk - cum;
            }
            __syncthreads();
            unsigned prefix = s_prefix;
            kk = s_kk;

            // refine bits 9..0 over candidates (1024 bins)
            hist[tid] = 0;
            __syncthreads();
            const unsigned hm = 0xFFFFFFFFu << 10;
            for (int i = tid; i < count; i += 1024) {
                unsigned key = s_cand[i];
                if ((key & hm) == prefix) atomicAdd(&hist[key & 1023], 1);
            }
            __syncthreads();
            if (tid < 32) {
                int s = 0;
                #pragma unroll
                for (int j = 0; j < 32; j++) s += hist[tid * 32 + j];
                s_group[tid] = s;
            }
            __syncthreads();
            if (tid == 0) {
                int cum = 0, g = 31;
                for (; g > 0; g--) {
                    if (cum + s_group[g] >= kk) break;
                    cum += s_group[g];
                }
                int x = g * 32 + 31;
                for (;; x--) {
                    int hv = hist[x];
                    if (cum + hv >= kk || x == g * 32) break;
                    cum += hv;
                }
                s_prefix = prefix | (unsigned)x;
                s_kk = kk - cum;
            }
            __syncthreads();
            prefix = s_prefix;
            kk = s_kk;

            // sum candidates above threshold + above-bin partials
            double local = hs;
            for (int i = tid; i < count; i += 1024) {
                unsigned key = s_cand[i];
                if (key > prefix) local += (double)__uint_as_float(key);
            }
            #pragma unroll
            for (int o = 16; o > 0; o >>= 1) local += __shfl_xor_sync(0xffffffffu, local, o);
            if (lane == 0) sdl[w] = local;
            __syncthreads();
            if (tid == 0) {
                double tot = 0.0;
                for (int i = 0; i < 32; i++) tot += sdl[i];
                tot += (double)kk * (double)__uint_as_float(prefix);
                atomicAdd(&g_ce_neg, tot);
            }
        } else {
            // ---- fallback: radix passes + global sum sweep ----
            unsigned prefix = bin << 21;
            const int shifts[2] = {10, 0};
            const int nbits [2] = {11, 10};
            #pragma unroll
            for (int pass = 0; pass < 2; pass++) {
                const int shift = shifts[pass];
                const int nb    = 1 << nbits[pass];
                hist[tid] = 0; hist[tid + 1024] = 0;
                __syncthreads();
                const unsigned hmask = 0xFFFFFFFFu << (shift + nbits[pass]);
                const unsigned bmask = (unsigned)(nb - 1);

                int i = tid;
                for (; i + 7 * 1024 < PP; i += 8 * 1024) {
                    unsigned kx[8];
                    #pragma unroll
                    for (int u = 0; u < 8; u++) kx[u] = __float_as_uint(lc[i + u * 1024]);
                    #pragma unroll
                    for (int u = 0; u < 8; u++)
                        if ((kx[u] & hmask) == prefix)
                            atomicAdd(&hist[(kx[u] >> shift) & bmask], 1);
                }
                for (; i < PP; i += 1024) {
                    unsigned key = __float_as_uint(lc[i]);
                    if ((key & hmask) == prefix) atomicAdd(&hist[(key >> shift) & bmask], 1);
                }
                __syncthreads();

                const int ngroups = nb >> 5;
                if (tid < ngroups) {
                    int s = 0;
                    #pragma unroll
                    for (int j = 0; j < 32; j++) s += hist[tid * 32 + j];
                    s_group[tid] = s;
                }
                __syncthreads();
                if (tid == 0) {
                    int cum = 0, g = ngroups - 1;
                    for (; g > 0; g--) {
                        if (cum + s_group[g] >= kk) break;
                        cum += s_group[g];
                    }
                    int x = g * 32 + 31;
                    for (;; x--) {
                        int hv = hist[x];
                        if (cum + hv >= kk || x == g * 32) break;
                        cum += hv;
                    }
                    s_prefix = prefix | ((unsigned)x << shift);
                    s_kk = kk - cum;
                }
                __syncthreads();
                prefix = s_prefix;
                kk     = s_kk;
            }

            double local = 0.0;
            {
                int i = tid;
                for (; i + 7 * 1024 < PP; i += 8 * 1024) {
                    float a[8];
                    #pragma unroll
                    for (int u = 0; u < 8; u++) a[u] = lc[i + u * 1024];
                    #pragma unroll
                    for (int u = 0; u < 8; u++)
                        if (__float_as_uint(a[u]) > prefix) local += (double)a[u];
                }
                for (; i < PP; i += 1024) {
                    float v = lc[i];
                    if (__float_as_uint(v) > prefix) local += (double)v;
                }
            }
            #pragma unroll
            for (int o = 16; o > 0; o >>= 1) local += __shfl_xor_sync(0xffffffffu, local, o);
            if (lane == 0) sdl[w] = local;
            __syncthreads();
            if (tid == 0) {
                double tot = 0.0;
                for (int i = 0; i < 32; i++) tot += sdl[i];
                tot += (double)kk * (double)__uint_as_float(prefix);
                atomicAdd(&g_ce_neg, tot);
            }
        }
    } else {
        // reset this batch's histogram for the next replay
        g_hist1[b * 2048 + tid] = 0;
        g_hist1[b * 2048 + 1024 + tid] = 0;
    }

    // ---- last-block finalize + state reset ----
    __syncthreads();
    if (tid == 0) {
        __threadfence();
        s_last = (atomicAdd(&g_ticket, 1) == BB - 1) ? 1 : 0;
    }
    __syncthreads();
    if (s_last) {
        if (tid == 0) {
            double N = (double)g_total_pos;
            if (N < 1.0) N = 1.0;
            out[0] = (float)(g_loss_l / N);
            out[1] = (float)((g_ce_pos + g_ce_neg) / N);
            g_total_pos = 0; g_loss_l = 0.0; g_ce_pos = 0.0; g_ce_neg = 0.0;
            g_ticket = 0;
        }
        g_bp_key[tid] = 0ULL;                   // BB*TT == 1024
        if (tid < BB) g_num_pos[tid] = 0;
    }
}

extern "C" void kernel_launch(void* const* d_in, const int* in_sizes, int n_in,
                              void* d_out, int out_size) {
    const float* loc_data  = (const float*)d_in[0];   // [B,P,4]
    const float* conf_data = (const float*)d_in[1];   // [B,P,81]
    const float* priors    = (const float*)d_in[2];   // [P,4]
    const float* targets   = (const float*)d_in[3];   // [B,T,5]
    float* out = (float*)d_out;

    match_kernel<<<dim3((PP + 255) / 256, BB), 256>>>(priors, targets);
    force_kernel<<<1, BB>>>();
    loss_kernel<<<dim3(LNBX, BB), 256>>>(loc_data, conf_data, priors, targets);
    mine_kernel<<<BB, 1024>>>(out);
}